// round 1
// baseline (speedup 1.0000x reference)
#include <cuda_runtime.h>
#include <cuda_bf16.h>
#include <cstdint>

// Problem constants
#define HH 128
#define WW 128
#define DD 64
#define HIDDEN 64
// mask volume 128x128x128, packed along x: 4 words per (z,y) row
#define MROW_WORDS 4
#define MASK_WORDS (128 * 128 * MROW_WORDS)

// ---------------- device scratch (no allocations allowed) ----------------
__device__ float4 g_cA[HIDDEN];          // A,B,C,D  (affine coeffs of u_j in px,py,pz,1)
__device__ float4 g_cB[HIDDEN];          // delta(=C*DZ), b1_j, W2_j, 0
__device__ unsigned g_mask[MASK_WORDS];  // bit-packed binary mask volume

// ---------------- prep: per-hidden affine coefficients ----------------
__global__ void prep_kernel(const float* __restrict__ T,
                            const float* __restrict__ W1,
                            const float* __restrict__ b1,
                            const float* __restrict__ W2) {
    int j = threadIdx.x;
    if (j >= HIDDEN) return;
    float w0 = W1[j], w1 = W1[HIDDEN + j], w2 = W1[2 * HIDDEN + j];
    // u_j = sum_d W1[d][j] * q_d,  q_d = T[d][0]*px + T[d][1]*py + T[d][2]*pz + T[d][3]
    float A = w0 * T[0] + w1 * T[4] + w2 * T[8];
    float B = w0 * T[1] + w1 * T[5] + w2 * T[9];
    float C = w0 * T[2] + w1 * T[6] + w2 * T[10];
    float Dc = w0 * T[3] + w1 * T[7] + w2 * T[11];
    g_cA[j] = make_float4(A, B, C, Dc);
    g_cB[j] = make_float4(C * 2.0f /* DZ */, b1[j], W2[j], 0.0f);
}

// ---------------- pack: float mask volume -> bits ----------------
__global__ void pack_kernel(const float* __restrict__ vol) {
    int idx = blockIdx.x * blockDim.x + threadIdx.x;  // one voxel per thread
    unsigned bal = __ballot_sync(0xffffffffu, vol[idx] != 0.0f);
    if ((threadIdx.x & 31) == 0) g_mask[idx >> 5] = bal;
}

// ---------------- main render ----------------
// grid: 512 blocks of 256 threads.
//   blockIdx.x & 127  -> jcol (py / W index)
//   blockIdx.x >> 7   -> i-tile (32 rows each)
//   lane (0..31)      -> i within tile
//   warp (0..7)       -> depth slot (8 consecutive k each)
__global__ __launch_bounds__(256) void render_kernel(const float* __restrict__ T4,
                                                     const float* __restrict__ b2p,
                                                     float* __restrict__ out) {
    __shared__ float4 sA[HIDDEN];
    __shared__ float4 sB[HIDDEN];
    __shared__ float red[8][32];

    int t = threadIdx.x;
    if (t < HIDDEN) sA[t] = g_cA[t];
    else if (t < 2 * HIDDEN) sB[t - HIDDEN] = g_cB[t - HIDDEN];
    __syncthreads();

    const int lane = t & 31;
    const int kslot = t >> 5;
    const int jcol = blockIdx.x & 127;
    const int i = ((blockIdx.x >> 7) << 5) + lane;

    const float t00 = __ldg(T4 + 0), t01 = __ldg(T4 + 1), t02 = __ldg(T4 + 2), t03 = __ldg(T4 + 3);
    const float t10 = __ldg(T4 + 4), t11 = __ldg(T4 + 5), t12 = __ldg(T4 + 6), t13 = __ldg(T4 + 7);
    const float t20 = __ldg(T4 + 8), t21 = __ldg(T4 + 9), t22 = __ldg(T4 + 10), t23 = __ldg(T4 + 11);
    const float t30 = __ldg(T4 + 12), t31 = __ldg(T4 + 13), t32 = __ldg(T4 + 14), t33 = __ldg(T4 + 15);

    const float px = (float)i - 63.5f;
    const float py = (float)jcol - 63.5f;

    float rcpw[8];
    unsigned mb = 0;  // per-k mask bits

    #pragma unroll
    for (int m = 0; m < 8; m++) {
        const int k = kslot * 8 + m;
        const float pz = ((float)k - 31.5f) * 2.0f;

        const float qx = fmaf(pz, t02, fmaf(py, t01, fmaf(px, t00, t03)));
        const float qy = fmaf(pz, t12, fmaf(py, t11, fmaf(px, t10, t13)));
        const float qz = fmaf(pz, t22, fmaf(py, t21, fmaf(px, t20, t23)));
        const float qw = fmaf(pz, t32, fmaf(py, t31, fmaf(px, t30, t33)));
        rcpw[m] = __fdiv_rn(1.0f, qw);

        // --- grid coords, mirroring reference float ops exactly (no contraction) ---
        const float xn = __fdiv_rn(qx, 63.5f);
        const float yn = __fdiv_rn(qy, 63.5f);
        const float zn = __fdiv_rn(qz, 63.5f);
        const float xg = __fmul_rn(__fmul_rn(__fadd_rn(xn, 1.0f), 0.5f), 127.0f);
        const float yg = __fmul_rn(__fmul_rn(__fadd_rn(yn, 1.0f), 0.5f), 127.0f);
        const float zg = __fmul_rn(__fmul_rn(__fadd_rn(zn, 1.0f), 0.5f), 127.0f);

        const float xf = floorf(xg), yf = floorf(yg), zf = floorf(zg);
        const float fx = xg - xf, fy = yg - yf, fz = zg - zf;
        const int x0 = (int)xf, y0 = (int)yf, z0 = (int)zf;

        // x-dimension candidates -> (word, bitmask) pairs
        const int x1 = x0 + 1;
        bool hA = (x0 >= 0) && (x0 <= 127);
        bool hB = (fx > 0.0f) && (x1 >= 0) && (x1 <= 127);
        int wA = x0 >> 5;
        unsigned bmA = 1u << (x0 & 31);
        const int wB = x1 >> 5;
        const unsigned bmB = 1u << (x1 & 31);
        if (hA && hB && (wA == wB)) { bmA |= bmB; hB = false; }
        if (!hA && hB) { wA = wB; bmA = bmB; hA = true; hB = false; }

        const int zz[2] = {z0, z0 + 1};
        const bool zv[2] = {(z0 >= 0) && (z0 <= 127),
                            (fz > 0.0f) && (z0 + 1 >= 0) && (z0 + 1 <= 127)};
        const int yy[2] = {y0, y0 + 1};
        const bool yv[2] = {(y0 >= 0) && (y0 <= 127),
                            (fy > 0.0f) && (y0 + 1 >= 0) && (y0 + 1 <= 127)};

        bool found = false;
        if (hA || hB) {
            #pragma unroll
            for (int a = 0; a < 2; a++) {
                #pragma unroll
                for (int b = 0; b < 2; b++) {
                    if (zv[a] && yv[b]) {
                        const int base = (((zz[a] << 7) + yy[b]) << 2);
                        unsigned hit = 0;
                        if (hA) hit = __ldg(&g_mask[base + wA]) & bmA;
                        if (hB) hit |= __ldg(&g_mask[base + wB]) & bmB;
                        found |= (hit != 0);
                    }
                }
            }
        }
        mb |= ((unsigned)found) << m;
    }

    // --- field MLP, incremental along depth ---
    float pot[8];
    #pragma unroll
    for (int m = 0; m < 8; m++) pot[m] = 0.0f;

    const float pz0 = ((float)(kslot * 8) - 31.5f) * 2.0f;
    const unsigned act = __ballot_sync(0xffffffffu, mb != 0);
    if (act) {
        #pragma unroll 4
        for (int jh = 0; jh < HIDDEN; jh++) {
            const float4 c = sA[jh];
            const float4 e = sB[jh];
            float u = fmaf(px, c.x, fmaf(py, c.y, fmaf(pz0, c.z, c.w)));
            #pragma unroll
            for (int m = 0; m < 8; m++) {
                const float a = fmaf(u, rcpw[m], e.y);
                const float h = fmaxf(a, 0.0f);
                pot[m] = fmaf(h, e.z, pot[m]);
                u += e.x;
            }
        }
    }

    const float b2v = __ldg(b2p);
    float part = 0.0f;
    #pragma unroll
    for (int m = 0; m < 8; m++)
        if ((mb >> m) & 1u) part += pot[m] + b2v;

    red[kslot][lane] = part;
    __syncthreads();
    if (kslot == 0) {
        float s = 0.0f;
        #pragma unroll
        for (int w = 0; w < 8; w++) s += red[w][lane];
        out[i * WW + jcol] = s * 2.0f;  // * DZ
    }
}

// ---------------- launch ----------------
extern "C" void kernel_launch(void* const* d_in, const int* in_sizes, int n_in,
                              void* d_out, int out_size) {
    const float* T  = (const float*)d_in[0];   // [1,4,4]
    const float* V  = (const float*)d_in[1];   // [128,128,128]
    const float* W1 = (const float*)d_in[2];   // [3,64]
    const float* b1 = (const float*)d_in[3];   // [64]
    const float* W2 = (const float*)d_in[4];   // [64,1]
    const float* b2 = (const float*)d_in[5];   // [1]
    float* out = (float*)d_out;                // [1,128,128]

    prep_kernel<<<1, HIDDEN>>>(T, W1, b1, W2);
    pack_kernel<<<(128 * 128 * 128) / 256, 256>>>(V);
    render_kernel<<<4 * 128, 256>>>(T, b2, out);
}

// round 2
// speedup vs baseline: 1.4415x; 1.4415x over previous
#include <cuda_runtime.h>
#include <cuda_bf16.h>
#include <cstdint>

#define HH 128
#define WW 128
#define HIDDEN 64
#define MROW_WORDS 4
#define MASK_WORDS (128 * 128 * MROW_WORDS)

// ---------------- device scratch ----------------
__device__ unsigned g_mask[MASK_WORDS];  // bit-packed binary mask volume

// ---------------- pack: float mask volume -> bits (float4 + shfl combine) ----
__global__ void pack_kernel(const float4* __restrict__ vol) {
    unsigned t = blockIdx.x * blockDim.x + threadIdx.x;  // 4 voxels / thread
    float4 v = vol[t];
    unsigned nib = (unsigned)(v.x != 0.0f)
                 | ((unsigned)(v.y != 0.0f) << 1)
                 | ((unsigned)(v.z != 0.0f) << 2)
                 | ((unsigned)(v.w != 0.0f) << 3);
    unsigned w = nib << (4 * (threadIdx.x & 7));
    w |= __shfl_xor_sync(0xffffffffu, w, 1);
    w |= __shfl_xor_sync(0xffffffffu, w, 2);
    w |= __shfl_xor_sync(0xffffffffu, w, 4);
    if ((threadIdx.x & 7) == 0) g_mask[t >> 3] = w;
}

// ---------------- fused render ----------------
// grid: 512 blocks x 256 threads.
//   blockIdx.x & 127 -> jcol ; blockIdx.x >> 7 -> i-tile (32 rows)
//   lane -> i within tile ; warp (0..7) -> depth slot (8 consecutive k)
__global__ __launch_bounds__(256) void render_kernel(const float* __restrict__ T4,
                                                     const float* __restrict__ W1,
                                                     const float* __restrict__ b1,
                                                     const float* __restrict__ W2p,
                                                     const float* __restrict__ b2p,
                                                     float* __restrict__ out) {
    __shared__ float4 sA[HIDDEN];        // A,B,C,D
    __shared__ float4 sB[HIDDEN];        // delta, D+b1, w2, -1/delta
    __shared__ float  sb1[HIDDEN];
    __shared__ float  sC0[9 * 256];      // per-thread masked suffix counts
    __shared__ float  sC1[9 * 256];      // per-thread masked suffix index-sums
    __shared__ float  red[8][32];

    const int t = threadIdx.x;

    // fused prep: per-hidden affine coefficients (redundant per block, tiny)
    if (t < HIDDEN) {
        float w0 = W1[t], w1 = W1[HIDDEN + t], w2 = W1[2 * HIDDEN + t];
        float A = w0 * T4[0] + w1 * T4[4] + w2 * T4[8];
        float B = w0 * T4[1] + w1 * T4[5] + w2 * T4[9];
        float C = w0 * T4[2] + w1 * T4[6] + w2 * T4[10];
        float D = w0 * T4[3] + w1 * T4[7] + w2 * T4[11];
        float dl = C * 2.0f;  // DZ
        sA[t] = make_float4(A, B, C, D);
        sB[t] = make_float4(dl, D + b1[t], W2p[t], -1.0f / dl);
        sb1[t] = b1[t];
    }
    __syncthreads();

    const int lane = t & 31;
    const int kslot = t >> 5;
    const int jcol = blockIdx.x & 127;
    const int i = ((blockIdx.x >> 7) << 5) + lane;

    const float t00 = __ldg(T4 + 0), t01 = __ldg(T4 + 1), t02 = __ldg(T4 + 2), t03 = __ldg(T4 + 3);
    const float t10 = __ldg(T4 + 4), t11 = __ldg(T4 + 5), t12 = __ldg(T4 + 6), t13 = __ldg(T4 + 7);
    const float t20 = __ldg(T4 + 8), t21 = __ldg(T4 + 9), t22 = __ldg(T4 + 10), t23 = __ldg(T4 + 11);
    const float t30 = __ldg(T4 + 12), t31 = __ldg(T4 + 13), t32 = __ldg(T4 + 14), t33 = __ldg(T4 + 15);
    const bool rigid = (t30 == 0.0f) && (t31 == 0.0f) && (t32 == 0.0f) && (t33 == 1.0f);

    const float px = (float)i - 63.5f;
    const float py = (float)jcol - 63.5f;

    float rcpw[8];
    unsigned mb = 0;  // per-k mask bits

    #pragma unroll
    for (int m = 0; m < 8; m++) {
        const int k = kslot * 8 + m;
        const float pz = ((float)k - 31.5f) * 2.0f;

        const float qx = fmaf(pz, t02, fmaf(py, t01, fmaf(px, t00, t03)));
        const float qy = fmaf(pz, t12, fmaf(py, t11, fmaf(px, t10, t13)));
        const float qz = fmaf(pz, t22, fmaf(py, t21, fmaf(px, t20, t23)));
        if (!rigid) {
            const float qw = fmaf(pz, t32, fmaf(py, t31, fmaf(px, t30, t33)));
            rcpw[m] = __fdiv_rn(1.0f, qw);
        }

        // grid coords, mirroring reference float ops exactly (no contraction)
        const float xn = __fdiv_rn(qx, 63.5f);
        const float yn = __fdiv_rn(qy, 63.5f);
        const float zn = __fdiv_rn(qz, 63.5f);
        const float xg = __fmul_rn(__fmul_rn(__fadd_rn(xn, 1.0f), 0.5f), 127.0f);
        const float yg = __fmul_rn(__fmul_rn(__fadd_rn(yn, 1.0f), 0.5f), 127.0f);
        const float zg = __fmul_rn(__fmul_rn(__fadd_rn(zn, 1.0f), 0.5f), 127.0f);

        const float xf = floorf(xg), yf = floorf(yg), zf = floorf(zg);
        const float fx = xg - xf, fy = yg - yf, fz = zg - zf;
        const int x0 = (int)xf, y0 = (int)yf, z0 = (int)zf;

        const int x1 = x0 + 1;
        bool hA = (x0 >= 0) && (x0 <= 127);
        bool hB = (fx > 0.0f) && (x1 >= 0) && (x1 <= 127);
        int wA = x0 >> 5;
        unsigned bmA = 1u << (x0 & 31);
        const int wB = x1 >> 5;
        const unsigned bmB = 1u << (x1 & 31);
        if (hA && hB && (wA == wB)) { bmA |= bmB; hB = false; }
        if (!hA && hB) { wA = wB; bmA = bmB; hA = true; hB = false; }

        const int zz[2] = {z0, z0 + 1};
        const bool zv[2] = {(z0 >= 0) && (z0 <= 127),
                            (fz > 0.0f) && (z0 + 1 >= 0) && (z0 + 1 <= 127)};
        const int yy[2] = {y0, y0 + 1};
        const bool yv[2] = {(y0 >= 0) && (y0 <= 127),
                            (fy > 0.0f) && (y0 + 1 >= 0) && (y0 + 1 <= 127)};

        bool found = false;
        if (hA || hB) {
            #pragma unroll
            for (int a = 0; a < 2; a++) {
                #pragma unroll
                for (int b = 0; b < 2; b++) {
                    if (zv[a] && yv[b]) {
                        const int base = (((zz[a] << 7) + yy[b]) << 2);
                        unsigned hit = 0;
                        if (hA) hit = __ldg(&g_mask[base + wA]) & bmA;
                        if (hB) hit |= __ldg(&g_mask[base + wB]) & bmB;
                        found |= (hit != 0);
                    }
                }
            }
        }
        mb |= ((unsigned)found) << m;
    }

    // ---- per-thread masked suffix tables: C0[s]=#set bits >= s, C1[s]=sum of indices
    {
        float c0 = 0.0f, c1 = 0.0f;
        sC0[8 * 256 + t] = 0.0f;
        sC1[8 * 256 + t] = 0.0f;
        #pragma unroll
        for (int s = 7; s >= 0; --s) {
            if ((mb >> s) & 1u) { c0 += 1.0f; c1 += (float)s; }
            sC0[s * 256 + t] = c0;
            sC1[s * 256 + t] = c1;
        }
    }
    const float tot0 = sC0[t];   // == popc(mb)
    const float tot1 = sC1[t];

    const float pz0 = ((float)(kslot * 8) - 31.5f) * 2.0f;
    const float b2v = __ldg(b2p);
    float part = 0.0f;

    const unsigned act = __ballot_sync(0xffffffffu, mb != 0);
    if (act) {
        if (rigid) {
            // analytic masked ReLU sum: a_m = u0 + m*delta (qw == 1 exactly)
            float acc = 0.0f;
            #pragma unroll 4
            for (int jh = 0; jh < HIDDEN; jh++) {
                const float4 c = sA[jh];
                const float4 e = sB[jh];  // delta, D+b1, w2, -1/delta
                const float u0 = fmaf(px, c.x, fmaf(py, c.y, fmaf(pz0, c.z, e.y)));
                const float g = u0 * e.w;          // = -u0/delta
                int tt = __float2int_ru(g);        // NaN->0, +inf->max, -inf->min
                tt = min(max(tt, 0), 8);
                const float C0t = sC0[tt * 256 + t];
                const float C1t = sC1[tt * 256 + t];
                float s0, s1;
                if (e.x < 0.0f) { s0 = tot0 - C0t; s1 = tot1 - C1t; }
                else            { s0 = C0t;        s1 = C1t; }
                acc = fmaf(e.z, fmaf(e.x, s1, u0 * s0), acc);
            }
            part = fmaf(b2v, tot0, acc);
        } else {
            // general path (homogeneous divide), exact per-sample eval
            float pot[8];
            #pragma unroll
            for (int m = 0; m < 8; m++) pot[m] = 0.0f;
            #pragma unroll 4
            for (int jh = 0; jh < HIDDEN; jh++) {
                const float4 c = sA[jh];
                const float4 e = sB[jh];
                const float bb = sb1[jh];
                float u = fmaf(px, c.x, fmaf(py, c.y, fmaf(pz0, c.z, c.w)));
                #pragma unroll
                for (int m = 0; m < 8; m++) {
                    const float a = fmaf(u, rcpw[m], bb);
                    const float h = fmaxf(a, 0.0f);
                    pot[m] = fmaf(h, e.z, pot[m]);
                    u += e.x;
                }
            }
            #pragma unroll
            for (int m = 0; m < 8; m++)
                if ((mb >> m) & 1u) part += pot[m] + b2v;
        }
    }

    red[kslot][lane] = part;
    __syncthreads();
    if (kslot == 0) {
        float s = 0.0f;
        #pragma unroll
        for (int w = 0; w < 8; w++) s += red[w][lane];
        out[i * WW + jcol] = s * 2.0f;  // * DZ
    }
}

// ---------------- launch ----------------
extern "C" void kernel_launch(void* const* d_in, const int* in_sizes, int n_in,
                              void* d_out, int out_size) {
    const float* T  = (const float*)d_in[0];   // [1,4,4]
    const float* V  = (const float*)d_in[1];   // [128,128,128]
    const float* W1 = (const float*)d_in[2];   // [3,64]
    const float* b1 = (const float*)d_in[3];   // [64]
    const float* W2 = (const float*)d_in[4];   // [64,1]
    const float* b2 = (const float*)d_in[5];   // [1]
    float* out = (float*)d_out;                // [1,128,128]

    pack_kernel<<<(128 * 128 * 128 / 4) / 256, 256>>>((const float4*)V);
    render_kernel<<<4 * 128, 256>>>(T, W1, b1, W2, b2, out);
}

// round 3
// speedup vs baseline: 1.7703x; 1.2280x over previous
#include <cuda_runtime.h>
#include <cuda_bf16.h>
#include <cstdint>

#define HIDDEN 64
#define BT 128          // threads per render block
#define SPT 16          // depth samples per thread
#define PROWS 17        // table rows per half (suffix 0..16, prefix 17..33)

__device__ unsigned g_mask[128 * 128 * 4];      // packed base mask
__device__ unsigned g_tab[8 * 128 * 128 * 4];   // 8 OR-dilation variants (dx,dy,dz)

// ---------------- pack: float volume -> bits ----------------
__global__ void pack_kernel(const float4* __restrict__ vol) {
    unsigned t = blockIdx.x * blockDim.x + threadIdx.x;  // 4 voxels / thread
    float4 v = vol[t];
    unsigned nib = (unsigned)(v.x != 0.0f) | ((unsigned)(v.y != 0.0f) << 1)
                 | ((unsigned)(v.z != 0.0f) << 2) | ((unsigned)(v.w != 0.0f) << 3);
    unsigned w = nib << (4 * (threadIdx.x & 7));
    w |= __shfl_xor_sync(0xffffffffu, w, 1);
    w |= __shfl_xor_sync(0xffffffffu, w, 2);
    w |= __shfl_xor_sync(0xffffffffu, w, 4);
    if ((threadIdx.x & 7) == 0) g_mask[t >> 3] = w;
}

// ---------------- dilate: build 8 OR variants (zero-padded) ----------------
__global__ void dilate_kernel() {
    int idx = blockIdx.x * blockDim.x + threadIdx.x;  // (z*128+y)*4+w, 65536 total
    int w = idx & 3, y = (idx >> 2) & 127, z = idx >> 9;
    bool yp = y < 127, zp = z < 127, wp = w < 3;
    unsigned r00 = g_mask[idx];
    unsigned r01 = yp ? g_mask[idx + 4] : 0u;
    unsigned r10 = zp ? g_mask[idx + 512] : 0u;
    unsigned r11 = (yp && zp) ? g_mask[idx + 516] : 0u;
    unsigned n00 = wp ? (g_mask[idx + 1] << 31) : 0u;   // bit0 of next word -> bit31
    unsigned n01 = (wp && yp) ? (g_mask[idx + 5] << 31) : 0u;
    unsigned n10 = (wp && zp) ? (g_mask[idx + 513] << 31) : 0u;
    unsigned n11 = (wp && yp && zp) ? (g_mask[idx + 517] << 31) : 0u;
    unsigned a2 = r00 | r01, a4 = r00 | r10, a6 = a2 | a4 | r11;
    unsigned m2 = n00 | n01, m4 = n00 | n10, m6 = m2 | m4 | n11;
    g_tab[idx]               = r00;                          // dx=0 dy=0 dz=0
    g_tab[1 * 65536 + idx]   = r00 | (r00 >> 1) | n00;       // dx=1
    g_tab[2 * 65536 + idx]   = a2;                           // dy=1
    g_tab[3 * 65536 + idx]   = a2 | (a2 >> 1) | m2;
    g_tab[4 * 65536 + idx]   = a4;                           // dz=1
    g_tab[5 * 65536 + idx]   = a4 | (a4 >> 1) | m4;
    g_tab[6 * 65536 + idx]   = a6;
    g_tab[7 * 65536 + idx]   = a6 | (a6 >> 1) | m6;
}

// ---------------- render ----------------
// grid 512 x 128 threads: blockIdx&127 -> jcol, blockIdx>>7 -> i-tile (32 rows)
// lane -> i ; warp (0..3) -> 16 consecutive depth samples
__global__ __launch_bounds__(BT) void render_kernel(const float* __restrict__ T4,
                                                    const float* __restrict__ W1,
                                                    const float* __restrict__ b1,
                                                    const float* __restrict__ W2p,
                                                    const float* __restrict__ b2p,
                                                    float* __restrict__ out) {
    __shared__ float4 sE[HIDDEN];            // A, delta, w2, -1/delta
    __shared__ float4 sBC[HIDDEN];           // B, C, D, b1
    __shared__ float  sV[4 * HIDDEN];        // per (kslot,hidden): py*B+pz0*C+(D+b1)
    __shared__ float2 sTab[2 * PROWS * BT];  // suffix rows 0..16, prefix rows 17..33
    __shared__ float  red[4][32];

    const int t = threadIdx.x;
    if (t < HIDDEN) {
        float w0 = W1[t], w1 = W1[HIDDEN + t], w2 = W1[2 * HIDDEN + t];
        float A = w0 * T4[0] + w1 * T4[4] + w2 * T4[8];
        float B = w0 * T4[1] + w1 * T4[5] + w2 * T4[9];
        float C = w0 * T4[2] + w1 * T4[6] + w2 * T4[10];
        float D = w0 * T4[3] + w1 * T4[7] + w2 * T4[11];
        float dl = C * 2.0f;  // DZ
        sE[t]  = make_float4(A, dl, W2p[t], -1.0f / dl);
        sBC[t] = make_float4(B, C, D, b1[t]);
    }
    __syncthreads();

    const int lane = t & 31;
    const int kslot = t >> 5;                 // 0..3
    const int jcol = blockIdx.x & 127;
    const int i = ((blockIdx.x >> 7) << 5) + lane;
    const float px = (float)i - 63.5f;
    const float py = (float)jcol - 63.5f;

    // per-(kslot,hidden) hoisted term (exact same composition as before)
    for (int s = t; s < 4 * HIDDEN; s += BT) {
        int jh = s & 63, ks = s >> 6;
        float pz0 = ((float)(ks * SPT) - 31.5f) * 2.0f;
        float4 bc = sBC[jh];
        float Db = bc.z + bc.w;
        sV[s] = fmaf(py, bc.x, fmaf(pz0, bc.y, Db));
    }
    __syncthreads();

    const float t00 = __ldg(T4 + 0), t01 = __ldg(T4 + 1), t02 = __ldg(T4 + 2), t03 = __ldg(T4 + 3);
    const float t10 = __ldg(T4 + 4), t11 = __ldg(T4 + 5), t12 = __ldg(T4 + 6), t13 = __ldg(T4 + 7);
    const float t20 = __ldg(T4 + 8), t21 = __ldg(T4 + 9), t22 = __ldg(T4 + 10), t23 = __ldg(T4 + 11);
    const float t30 = __ldg(T4 + 12), t31 = __ldg(T4 + 13), t32 = __ldg(T4 + 14), t33 = __ldg(T4 + 15);
    const bool rigid = (t30 == 0.0f) && (t31 == 0.0f) && (t32 == 0.0f) && (t33 == 1.0f);

    // hoisted lane-constant parts (identical rounding to nested fmaf chain)
    const float cx = fmaf(py, t01, fmaf(px, t00, t03));
    const float cy = fmaf(py, t11, fmaf(px, t10, t13));
    const float cz = fmaf(py, t21, fmaf(px, t20, t23));
    const float cw = fmaf(py, t31, fmaf(px, t30, t33));

    const float EPS = 2e-4f;
    unsigned mb = 0;
    float pz = ((float)(kslot * SPT) - 31.5f) * 2.0f;  // exact integers, exact increments

    #pragma unroll 4
    for (int m = 0; m < SPT; m++) {
        const float qx = fmaf(pz, t02, cx);
        const float qy = fmaf(pz, t12, cy);
        const float qz = fmaf(pz, t22, cz);

        // fast coordinates: xg == ((qx/63.5+1)*0.5)*127 mathematically
        float xg = qx + 63.5f, yg = qy + 63.5f, zg = qz + 63.5f;
        float xf = floorf(xg), yf = floorf(yg), zf = floorf(zg);
        float fx = xg - xf, fy = yg - yf, fz = zg - zf;
        // guard: if any frac within EPS of 0/1, fp path difference could flip a decision
        float dmin = fminf(fminf(fminf(fx, 1.0f - fx), fminf(fy, 1.0f - fy)),
                           fminf(fz, 1.0f - fz));
        int x0, y0, z0;
        bool bx, by, bz;  // frac > 0 flags
        if (__any_sync(0xffffffffu, dmin < EPS)) {
            // exact reference-matching recompute (rare)
            float xn = __fdiv_rn(qx, 63.5f), yn = __fdiv_rn(qy, 63.5f), zn = __fdiv_rn(qz, 63.5f);
            float xge = __fmul_rn(__fmul_rn(__fadd_rn(xn, 1.0f), 0.5f), 127.0f);
            float yge = __fmul_rn(__fmul_rn(__fadd_rn(yn, 1.0f), 0.5f), 127.0f);
            float zge = __fmul_rn(__fmul_rn(__fadd_rn(zn, 1.0f), 0.5f), 127.0f);
            float xfe = floorf(xge), yfe = floorf(yge), zfe = floorf(zge);
            x0 = (int)xfe; y0 = (int)yfe; z0 = (int)zfe;
            bx = xge > xfe; by = yge > yfe; bz = zge > zfe;
        } else {
            x0 = (int)xf; y0 = (int)yf; z0 = (int)zf;
            bx = true; by = true; bz = true;  // frac in [EPS,1-EPS] => exact frac > 0
        }

        const bool okx = (x0 >= -1) && (x0 <= 127) && (bx || x0 >= 0);
        const bool oky = (y0 >= -1) && (y0 <= 127) && (by || y0 >= 0);
        const bool okz = (z0 >= -1) && (z0 <= 127) && (bz || z0 >= 0);
        unsigned bit = 0;
        if (okx && oky && okz) {
            const int dxk = (bx && x0 >= 0) ? 1 : 0;
            const int dyk = (by && y0 >= 0) ? 1 : 0;
            const int dzk = (bz && z0 >= 0) ? 1 : 0;
            const int xb = max(x0, 0), yb = max(y0, 0), zb = max(z0, 0);
            const int widx = ((dxk | (dyk << 1) | (dzk << 2)) << 16)
                           | (zb << 9) | (yb << 2) | (xb >> 5);
            bit = (__ldg(&g_tab[widx]) >> (xb & 31)) & 1u;
        }
        mb |= bit << m;
        pz += 2.0f;
    }

    // ---- per-thread suffix (rows 0..16) and prefix (rows 17..33) tables ----
    float2* tb = sTab + t;
    {
        float c0 = 0.0f, c1 = 0.0f;
        tb[16 * BT] = make_float2(0.0f, 0.0f);
        #pragma unroll
        for (int s = SPT - 1; s >= 0; --s) {
            if ((mb >> s) & 1u) { c0 += 1.0f; c1 += (float)s; }
            tb[s * BT] = make_float2(c0, c1);
        }
        float p0 = 0.0f, p1 = 0.0f;
        tb[17 * BT] = make_float2(0.0f, 0.0f);
        #pragma unroll
        for (int s = 0; s < SPT; ++s) {
            if ((mb >> s) & 1u) { p0 += 1.0f; p1 += (float)s; }
            tb[(18 + s) * BT] = make_float2(p0, p1);
        }
    }
    const float2 totp = tb[0];
    const float tot0 = totp.x;

    const float b2v = __ldg(b2p);
    float part = 0.0f;

    const unsigned act = __ballot_sync(0xffffffffu, mb != 0);
    if (act) {
        if (rigid) {
            const float* sVk = sV + kslot * HIDDEN;
            float acc0 = 0.0f, acc1 = 0.0f;
            #pragma unroll 16
            for (int jh = 0; jh < HIDDEN; jh += 2) {
                {
                    float4 e = sE[jh];
                    float u0 = fmaf(px, e.x, sVk[jh]);
                    float g = u0 * e.w;
                    int tt = __float2int_ru(g);
                    tt = min(max(tt, 0), SPT);
                    if (e.w > 0.0f) tt += PROWS;   // delta<0 -> prefix rows
                    float2 s = tb[tt * BT];
                    acc0 = fmaf(e.z, fmaf(e.y, s.y, u0 * s.x), acc0);
                }
                {
                    float4 e = sE[jh + 1];
                    float u0 = fmaf(px, e.x, sVk[jh + 1]);
                    float g = u0 * e.w;
                    int tt = __float2int_ru(g);
                    tt = min(max(tt, 0), SPT);
                    if (e.w > 0.0f) tt += PROWS;
                    float2 s = tb[tt * BT];
                    acc1 = fmaf(e.z, fmaf(e.y, s.y, u0 * s.x), acc1);
                }
            }
            part = fmaf(b2v, tot0, acc0 + acc1);
        } else {
            // general path: homogeneous divide, per-sample exact eval (correctness fallback)
            float pot = 0.0f;
            for (int m = 0; m < SPT; m++) {
                if ((mb >> m) & 1u) {
                    float pzm = ((float)(kslot * SPT + m) - 31.5f) * 2.0f;
                    float qw = fmaf(pzm, t32, cw);
                    float rcp = __fdiv_rn(1.0f, qw);
                    float s = 0.0f;
                    for (int jh = 0; jh < HIDDEN; jh++) {
                        float4 e = sE[jh];
                        float4 bc = sBC[jh];
                        float u = fmaf(px, e.x, fmaf(py, bc.x, fmaf(pzm, bc.y, bc.z)));
                        float a = fmaf(u, rcp, bc.w);
                        s = fmaf(fmaxf(a, 0.0f), e.z, s);
                    }
                    pot += s + b2v;
                }
            }
            part = pot;
        }
    }

    red[kslot][lane] = part;
    __syncthreads();
    if (kslot == 0) {
        float s = ((red[0][lane] + red[1][lane]) + red[2][lane]) + red[3][lane];
        out[i * 128 + jcol] = s * 2.0f;  // * DZ
    }
}

// ---------------- launch ----------------
extern "C" void kernel_launch(void* const* d_in, const int* in_sizes, int n_in,
                              void* d_out, int out_size) {
    const float* T  = (const float*)d_in[0];
    const float* V  = (const float*)d_in[1];
    const float* W1 = (const float*)d_in[2];
    const float* b1 = (const float*)d_in[3];
    const float* W2 = (const float*)d_in[4];
    const float* b2 = (const float*)d_in[5];
    float* out = (float*)d_out;

    pack_kernel<<<(128 * 128 * 128 / 4) / 256, 256>>>((const float4*)V);
    dilate_kernel<<<65536 / 256, 256>>>();
    render_kernel<<<4 * 128, BT>>>(T, W1, b1, W2, b2, out);
}